// round 8
// baseline (speedup 1.0000x reference)
#include <cuda_runtime.h>

#define NN   128
#define BB   32
#define INF  4608
#define KSPLIT 36    // 4608 / 128
#define KSEG   128

// ---------------- device scratch ----------------
__device__ float g_qsum[NN];              // qsum[i] = sum_n Q[n][i]
__device__ float g_q127[NN];              // q127[n] = Q[n][127]
__device__ float g_nsum[NN];              // nsum[d] = sum_n ns[n][d]
__device__ float g_P[KSPLIT * BB * NN];   // split-K partials of x @ Wt
__device__ float g_Qp[4 * NN * NN];       // partial Q: [jq][i][n]
__device__ float g_M0T[NN * NN];          // M0T[i][d] = sum_n ns[n][d] Q[n][i]
__device__ float g_out[BB * NN];          // out[b][d]

// ---------------- K1 (fused): ev partial-reduce ; nsum ; input GEMM ----------------
__global__ void __launch_bounds__(256) k_fused1(const float* __restrict__ ev,
                                                const float* __restrict__ ns,
                                                const float* __restrict__ x,
                                                const float* __restrict__ w) {
    int bi = blockIdx.x;
    int t  = threadIdx.x;
    if (bi < 4 * NN) {
        // ---- partial Q: Qp[jq][i][n] = sum_{j in quarter} ev[i][j][n] ----
        __shared__ float4 sred[256];
        int i  = bi >> 2;
        int jq = bi & 3;
        int n4 = t & 31;            // float4 index over n
        int jl = t >> 5;            // 0..7
        const float4* p4 = (const float4*)(ev + (size_t)i * NN * NN);  // [128][32]
        float4 a = make_float4(0.f, 0.f, 0.f, 0.f);
        #pragma unroll
        for (int r = 0; r < 4; r++) {
            float4 v = p4[(jq * 32 + jl + r * 8) * 32 + n4];
            a.x += v.x; a.y += v.y; a.z += v.z; a.w += v.w;
        }
        sred[t] = a;
        __syncthreads();
        if (jl < 4) {
            float4 b = sred[t + 128];
            a.x += b.x; a.y += b.y; a.z += b.z; a.w += b.w;
            sred[t] = a;
        }
        __syncthreads();
        if (jl < 2) {
            float4 b = sred[t + 64];
            a.x += b.x; a.y += b.y; a.z += b.z; a.w += b.w;
            sred[t] = a;
        }
        __syncthreads();
        if (jl == 0) {
            float4 b = sred[t + 32];
            a.x += b.x; a.y += b.y; a.z += b.z; a.w += b.w;
            ((float4*)g_Qp)[(jq * NN + i) * 32 + n4] = a;
        }
    } else if (bi == 4 * NN) {
        // ---- nsum[d] = sum_n ns[n][d] ----
        if (t < NN) {
            float acc = 0.f;
            #pragma unroll 16
            for (int n = 0; n < NN; n++) acc += ns[n * NN + t];
            g_nsum[t] = acc;
        }
    } else {
        // ---- input GEMM split-K: idx in [0,144) -> (s, db) ----
        __shared__ float xs[32 * 65];
        __shared__ float ws[32 * 65];
        int idx = bi - 4 * NN - 1;
        int s   = idx >> 2;          // 0..35
        int db  = idx & 3;           // 0..3
        int k0  = s * KSEG;
        int d0  = db * 32;
        int bq = t & 15, dq = t >> 4;
        float a00 = 0.f, a01 = 0.f, a10 = 0.f, a11 = 0.f;
        for (int kc = 0; kc < KSEG; kc += 64) {
            #pragma unroll
            for (int i = 0; i < 2; i++) {
                int e  = t + i * 256;          // 512 float4 = 32 rows x 16 f4
                int r  = e >> 4, c4 = e & 15;
                float4 xv = *(const float4*)&x[r * INF + k0 + kc + c4 * 4];
                float4 wv = *(const float4*)&w[(d0 + r) * INF + k0 + kc + c4 * 4];
                int o = r * 65 + c4 * 4;
                xs[o + 0] = xv.x; xs[o + 1] = xv.y; xs[o + 2] = xv.z; xs[o + 3] = xv.w;
                ws[o + 0] = wv.x; ws[o + 1] = wv.y; ws[o + 2] = wv.z; ws[o + 3] = wv.w;
            }
            __syncthreads();
            #pragma unroll
            for (int k = 0; k < 64; k++) {
                float xb0 = xs[(2 * bq) * 65 + k];
                float xb1 = xs[(2 * bq + 1) * 65 + k];
                float wd0 = ws[(2 * dq) * 65 + k];
                float wd1 = ws[(2 * dq + 1) * 65 + k];
                a00 += xb0 * wd0; a01 += xb0 * wd1;
                a10 += xb1 * wd0; a11 += xb1 * wd1;
            }
            __syncthreads();
        }
        int b0 = 2 * bq, dl = 2 * dq;
        g_P[(s * BB + b0) * NN + d0 + dl]           = a00;
        g_P[(s * BB + b0) * NN + d0 + dl + 1]       = a01;
        g_P[(s * BB + b0 + 1) * NN + d0 + dl]       = a10;
        g_P[(s * BB + b0 + 1) * NN + d0 + dl + 1]   = a11;
    }
}

// ---------------- K2: M0T[i][d] = sum_n Q[n][i] ns[n][d]; qsum; q127 ----------------
__global__ void __launch_bounds__(256) k_M0(const float* __restrict__ ns) {
    __shared__ float Qs[NN * 33];   // [n][il]
    __shared__ float Ns[NN * 33];   // [n][dl]
    int i0 = blockIdx.x * 32;
    int d0 = blockIdx.y * 32;
    int t  = threadIdx.x;
    // build Qs: Q[n][i0+il] = sum_jq Qp[jq][i0+il][n]
    #pragma unroll
    for (int rep = 0; rep < 16; rep++) {
        int idx = t + rep * 256;
        int il = idx >> 7, n = idx & 127;
        float s = 0.f;
        #pragma unroll
        for (int jq = 0; jq < 4; jq++)
            s += g_Qp[(jq * NN + i0 + il) * NN + n];
        Qs[n * 33 + il] = s;
    }
    // load Ns
    #pragma unroll
    for (int rep = 0; rep < 16; rep++) {
        int idx = t + rep * 256;
        int n = idx >> 5, dl = idx & 31;
        Ns[n * 33 + dl] = ns[n * NN + d0 + dl];
    }
    __syncthreads();
    int il2 = 2 * (t >> 4), dl2 = 2 * (t & 15);
    float a00 = 0.f, a01 = 0.f, a10 = 0.f, a11 = 0.f;
    #pragma unroll 8
    for (int n = 0; n < NN; n++) {
        float q0 = Qs[n * 33 + il2], q1 = Qs[n * 33 + il2 + 1];
        float s0 = Ns[n * 33 + dl2], s1 = Ns[n * 33 + dl2 + 1];
        a00 += q0 * s0; a01 += q0 * s1;
        a10 += q1 * s0; a11 += q1 * s1;
    }
    g_M0T[(i0 + il2) * NN + d0 + dl2]           = a00;
    g_M0T[(i0 + il2) * NN + d0 + dl2 + 1]       = a01;
    g_M0T[(i0 + il2 + 1) * NN + d0 + dl2]       = a10;
    g_M0T[(i0 + il2 + 1) * NN + d0 + dl2 + 1]   = a11;
    if (blockIdx.y == 0) {
        if (t < 32) {
            float s = 0.f;
            #pragma unroll 8
            for (int n = 0; n < NN; n++) s += Qs[n * 33 + t];
            g_qsum[i0 + t] = s;
        }
        if (blockIdx.x == 3 && t < NN)
            g_q127[t] = Qs[t * 33 + 31];   // Q[n][127]
    }
}

// ---------------- K3: fused step1 closed-form + step2 reduction (8-way i-split) ----------------
__global__ void __launch_bounds__(1024) k_final(const float* __restrict__ ib) {
    int b  = blockIdx.x;
    int t  = threadIdx.x;
    int d  = t & 127;
    int iq = t >> 7;                 // 0..7
    __shared__ float qs_s[NN], q127_s[NN], xt_s[NN], s1_s[NN];
    __shared__ float pc[8][NN], ps[8][NN];
    float xp = 0.f;
    #pragma unroll
    for (int s = iq; s < KSPLIT; s += 8) xp += g_P[(s * BB + b) * NN + d];
    pc[iq][d] = xp;
    if (t < NN) {
        qs_s[t]   = g_qsum[t];
        q127_s[t] = g_q127[t];
    }
    __syncthreads();
    if (t < NN) {
        float xt = ib[t];
        #pragma unroll
        for (int q = 0; q < 8; q++) xt += pc[q][t];
        xt_s[t] = xt;
        s1_s[t] = g_nsum[t] + 128.f * xt;
    }
    __syncthreads();
    float xt = xt_s[d], s1 = s1_s[d];
    float c = 0.f, ss = 0.f;
    int i0 = iq * 16;
    #pragma unroll
    for (int k = 0; k < 16; k++) {
        int i = i0 + k;
        float v = (g_M0T[i * NN + d] + xt * qs_s[i]) * s1;
        v = (i == d) ? 0.f : fmaxf(v, 0.f);
        c  += v * q127_s[i];
        ss += v;
    }
    pc[iq][d] = c; ps[iq][d] = ss;
    __syncthreads();
    if (t < NN) {
        float C = 0.f, S = 0.f;
        #pragma unroll
        for (int q = 0; q < 8; q++) { C += pc[q][d]; S += ps[q][d]; }
        float m = C * S;
        if (d == 127) m = 0.f;
        g_out[b * NN + d] = fmaxf(m, 0.f);
    }
}

// ---------------- K4: recreation GEMM + scores ----------------
__global__ void __launch_bounds__(256) k_heads(const float* __restrict__ rw,
                                               const float* __restrict__ rb,
                                               const float* __restrict__ sw,
                                               const float* __restrict__ sb,
                                               float* __restrict__ out,
                                               int score_off) {
    int bx = blockIdx.x;
    int t  = threadIdx.x;
    if (bx < 144) {
        __shared__ float os[32 * 129];
        __shared__ float ws[32 * 129];
        int f0 = bx * 32;
        #pragma unroll
        for (int i = 0; i < 4; i++) {
            int e  = t + i * 256;          // 1024 float4 = 32 rows x 32 f4
            int r  = e >> 5, c4 = e & 31;
            float4 ov = ((const float4*)&g_out[r * NN])[c4];
            float4 wv = ((const float4*)&rw[(size_t)(f0 + r) * NN])[c4];
            int o = r * 129 + c4 * 4;
            os[o + 0] = ov.x; os[o + 1] = ov.y; os[o + 2] = ov.z; os[o + 3] = ov.w;
            ws[o + 0] = wv.x; ws[o + 1] = wv.y; ws[o + 2] = wv.z; ws[o + 3] = wv.w;
        }
        __syncthreads();
        int bq = t & 15, fq = t >> 4;
        int b0 = 2 * bq, fl = 2 * fq;
        float a00 = 0.f, a01 = 0.f, a10 = 0.f, a11 = 0.f;
        #pragma unroll 8
        for (int k = 0; k < NN; k++) {
            float xb0 = os[b0 * 129 + k];
            float xb1 = os[(b0 + 1) * 129 + k];
            float w0  = ws[fl * 129 + k];
            float w1  = ws[(fl + 1) * 129 + k];
            a00 += xb0 * w0; a01 += xb0 * w1;
            a10 += xb1 * w0; a11 += xb1 * w1;
        }
        float rb0 = rb[f0 + fl], rb1 = rb[f0 + fl + 1];
        out[b0 * INF + f0 + fl]           = a00 + rb0;
        out[b0 * INF + f0 + fl + 1]       = a01 + rb1;
        out[(b0 + 1) * INF + f0 + fl]     = a10 + rb0;
        out[(b0 + 1) * INF + f0 + fl + 1] = a11 + rb1;
    } else {
        if (t < BB) {
            float acc = sb[0];
            #pragma unroll 8
            for (int d = 0; d < NN; d++) acc += g_out[t * NN + d] * sw[d];
            out[score_off + t] = acc;
        }
    }
}

// ---------------- launch ----------------
extern "C" void kernel_launch(void* const* d_in, const int* in_sizes, int n_in,
                              void* d_out, int out_size) {
    const float* x   = (const float*)d_in[0];
    const float* ipw = (const float*)d_in[1];
    const float* ipb = (const float*)d_in[2];
    const float* ns  = (const float*)d_in[3];
    const float* ev  = (const float*)d_in[4];
    const float* rw  = (const float*)d_in[5];
    const float* rb  = (const float*)d_in[6];
    const float* sw  = (const float*)d_in[7];
    const float* sb  = (const float*)d_in[8];
    float* out = (float*)d_out;

    k_fused1<<<4 * NN + 1 + 144, 256>>>(ev, ns, x, ipw);
    k_M0    <<<dim3(4, 4), 256>>>(ns);
    k_final <<<BB, 1024>>>(ipb);
    k_heads <<<145, 256>>>(rw, rb, sw, sb, out, out_size - BB);
}

// round 9
// speedup vs baseline: 1.4443x; 1.4443x over previous
#include <cuda_runtime.h>

#define NN   128
#define BB   32
#define INF  4608
#define KSPLIT 36    // 4608 / 128
#define KSEG   128

// ---------------- device scratch ----------------
__device__ float g_qsum[NN];              // qsum[i] = sum_n Q[n][i]
__device__ float g_q127[NN];              // q127[n] = Q[n][127]
__device__ float g_nsum[NN];              // nsum[d] = sum_n ns[n][d]
__device__ float g_P[KSPLIT * BB * NN];   // split-K partials of x @ Wt
__device__ float g_M0T[NN * NN];          // M0T[i][d] = sum_n ns[n][d] Q[n][i]
__device__ float g_out[BB * NN];          // out[b][d]

// ---------------- K1 (fused): ev-reduce -> qsum/q127/M0T ; nsum ; input GEMM ----------------
__global__ void __launch_bounds__(256) k_fused1(const float* __restrict__ ev,
                                                const float* __restrict__ ns,
                                                const float* __restrict__ x,
                                                const float* __restrict__ w) {
    int bi = blockIdx.x;
    int t  = threadIdx.x;
    if (bi < NN) {
        // ---- per-i: qv[n] = Q[n][i] = sum_j ev[i][j][n] (float4 over n) ----
        __shared__ float4 sred[256];
        __shared__ float  qsh[NN];
        __shared__ float  pd[256];
        int i  = bi;
        int n4 = t & 31;            // float4 index over n (32 x 4 = 128)
        int j0 = t >> 5;            // 0..7
        const float4* p4 = (const float4*)(ev + (size_t)i * NN * NN);  // [128][32]
        float4 a = make_float4(0.f, 0.f, 0.f, 0.f);
        #pragma unroll
        for (int j = j0; j < NN; j += 8) {
            float4 v = p4[j * 32 + n4];
            a.x += v.x; a.y += v.y; a.z += v.z; a.w += v.w;
        }
        sred[t] = a;
        __syncthreads();
        if (j0 < 4) {
            float4 b = sred[t + 128];
            a.x += b.x; a.y += b.y; a.z += b.z; a.w += b.w;
            sred[t] = a;
        }
        __syncthreads();
        if (j0 < 2) {
            float4 b = sred[t + 64];
            a.x += b.x; a.y += b.y; a.z += b.z; a.w += b.w;
            sred[t] = a;
        }
        __syncthreads();
        if (j0 == 0) {
            float4 b = sred[t + 32];
            a.x += b.x; a.y += b.y; a.z += b.z; a.w += b.w;
            qsh[4 * n4 + 0] = a.x; qsh[4 * n4 + 1] = a.y;
            qsh[4 * n4 + 2] = a.z; qsh[4 * n4 + 3] = a.w;
            if (i == 127) ((float4*)g_q127)[n4] = a;       // Q[n][127]
            float s = a.x + a.y + a.z + a.w;
            #pragma unroll
            for (int off = 16; off > 0; off >>= 1)
                s += __shfl_xor_sync(0xffffffffu, s, off);
            if (n4 == 0) g_qsum[i] = s;
        }
        __syncthreads();
        // M0T[i][d] = sum_n qsh[n] * ns[n][d]  (split n across 2 halves)
        int d = t & 127, h = t >> 7;
        float m = 0.f;
        int nb = h * 64;
        #pragma unroll 8
        for (int k = 0; k < 64; k++) m += qsh[nb + k] * ns[(nb + k) * NN + d];
        pd[t] = m;
        __syncthreads();
        if (t < NN) g_M0T[i * NN + t] = pd[t] + pd[t + 128];
    } else if (bi == NN) {
        // ---- nsum[d] = sum_n ns[n][d] ----
        if (t < NN) {
            float acc = 0.f;
            #pragma unroll 16
            for (int n = 0; n < NN; n++) acc += ns[n * NN + t];
            g_nsum[t] = acc;
        }
    } else {
        // ---- input GEMM split-K: idx in [0,144) -> (s, db) ----
        __shared__ float xs[32 * 65];
        __shared__ float ws[32 * 65];
        int idx = bi - NN - 1;
        int s   = idx >> 2;          // 0..35
        int db  = idx & 3;           // 0..3
        int k0  = s * KSEG;
        int d0  = db * 32;
        int bq = t & 15, dq = t >> 4;
        float a00 = 0.f, a01 = 0.f, a10 = 0.f, a11 = 0.f;
        for (int kc = 0; kc < KSEG; kc += 64) {
            #pragma unroll
            for (int i = 0; i < 2; i++) {
                int e  = t + i * 256;          // 512 float4 = 32 rows x 16 f4
                int r  = e >> 4, c4 = e & 15;
                float4 xv = *(const float4*)&x[r * INF + k0 + kc + c4 * 4];
                float4 wv = *(const float4*)&w[(d0 + r) * INF + k0 + kc + c4 * 4];
                int o = r * 65 + c4 * 4;
                xs[o + 0] = xv.x; xs[o + 1] = xv.y; xs[o + 2] = xv.z; xs[o + 3] = xv.w;
                ws[o + 0] = wv.x; ws[o + 1] = wv.y; ws[o + 2] = wv.z; ws[o + 3] = wv.w;
            }
            __syncthreads();
            #pragma unroll
            for (int k = 0; k < 64; k++) {
                float xb0 = xs[(2 * bq) * 65 + k];
                float xb1 = xs[(2 * bq + 1) * 65 + k];
                float wd0 = ws[(2 * dq) * 65 + k];
                float wd1 = ws[(2 * dq + 1) * 65 + k];
                a00 += xb0 * wd0; a01 += xb0 * wd1;
                a10 += xb1 * wd0; a11 += xb1 * wd1;
            }
            __syncthreads();
        }
        int b0 = 2 * bq, dl = 2 * dq;
        g_P[(s * BB + b0) * NN + d0 + dl]           = a00;
        g_P[(s * BB + b0) * NN + d0 + dl + 1]       = a01;
        g_P[(s * BB + b0 + 1) * NN + d0 + dl]       = a10;
        g_P[(s * BB + b0 + 1) * NN + d0 + dl + 1]   = a11;
    }
}

// ---------------- K2: fused step1 closed-form + step2 reduction (8-way i-split) ----------------
__global__ void __launch_bounds__(1024) k_final(const float* __restrict__ ib) {
    int b  = blockIdx.x;
    int t  = threadIdx.x;
    int d  = t & 127;
    int iq = t >> 7;                 // 0..7
    __shared__ float qs_s[NN], q127_s[NN], xt_s[NN], s1_s[NN];
    __shared__ float pc[8][NN], ps[8][NN];
    float xp = 0.f;
    #pragma unroll
    for (int s = iq; s < KSPLIT; s += 8) xp += g_P[(s * BB + b) * NN + d];
    pc[iq][d] = xp;
    if (t < NN) {
        qs_s[t]   = g_qsum[t];
        q127_s[t] = g_q127[t];
    }
    __syncthreads();
    if (t < NN) {
        float xt = ib[t];
        #pragma unroll
        for (int q = 0; q < 8; q++) xt += pc[q][t];
        xt_s[t] = xt;
        s1_s[t] = g_nsum[t] + 128.f * xt;
    }
    __syncthreads();
    float xt = xt_s[d], s1 = s1_s[d];
    float c = 0.f, ss = 0.f;
    int i0 = iq * 16;
    #pragma unroll
    for (int k = 0; k < 16; k++) {
        int i = i0 + k;
        float v = (g_M0T[i * NN + d] + xt * qs_s[i]) * s1;
        v = (i == d) ? 0.f : fmaxf(v, 0.f);
        c  += v * q127_s[i];
        ss += v;
    }
    pc[iq][d] = c; ps[iq][d] = ss;
    __syncthreads();
    if (t < NN) {
        float C = 0.f, S = 0.f;
        #pragma unroll
        for (int q = 0; q < 8; q++) { C += pc[q][d]; S += ps[q][d]; }
        float m = C * S;
        if (d == 127) m = 0.f;
        g_out[b * NN + d] = fmaxf(m, 0.f);
    }
}

// ---------------- K3: recreation GEMM (16-feature tiles, LDS.128 inner loop) + scores ----------------
#define FP 34   // padded row width in float4 (136 floats)
__global__ void __launch_bounds__(256) k_heads(const float* __restrict__ rw,
                                               const float* __restrict__ rb,
                                               const float* __restrict__ sw,
                                               const float* __restrict__ sb,
                                               float* __restrict__ out,
                                               int score_off) {
    int bx = blockIdx.x;
    int t  = threadIdx.x;
    if (bx < 288) {
        __shared__ float4 os4[32 * FP];   // os[b][k], pad 136 floats
        __shared__ float4 ws4[16 * FP];   // ws[f][k], pad 136 floats
        int f0 = bx * 16;
        // stage g_out: 1024 float4, coalesced
        #pragma unroll
        for (int i = 0; i < 4; i++) {
            int e = t + i * 256;
            int r = e >> 5, c4 = e & 31;
            os4[r * FP + c4] = ((const float4*)&g_out[r * NN])[c4];
        }
        // stage weights: 512 float4, coalesced
        #pragma unroll
        for (int i = 0; i < 2; i++) {
            int e = t + i * 256;
            int r = e >> 5, c4 = e & 31;
            ws4[r * FP + c4] = ((const float4*)&rw[(size_t)(f0 + r) * NN])[c4];
        }
        __syncthreads();
        int bq = t >> 4;          // 0..15 -> batches 2bq, 2bq+1
        int fq = t & 15;          // 0..15 -> feature f0+fq
        float a0 = 0.f, a1 = 0.f;
        const float4* osr0 = &os4[(2 * bq) * FP];
        const float4* osr1 = &os4[(2 * bq + 1) * FP];
        const float4* wsr  = &ws4[fq * FP];
        #pragma unroll
        for (int k4 = 0; k4 < 32; k4++) {
            float4 wv  = wsr[k4];
            float4 x0  = osr0[k4];
            float4 x1  = osr1[k4];
            a0 += x0.x * wv.x + x0.y * wv.y + x0.z * wv.z + x0.w * wv.w;
            a1 += x1.x * wv.x + x1.y * wv.y + x1.z * wv.z + x1.w * wv.w;
        }
        float bias = rb[f0 + fq];
        out[(2 * bq) * INF + f0 + fq]     = a0 + bias;
        out[(2 * bq + 1) * INF + f0 + fq] = a1 + bias;
    } else {
        if (t < BB) {
            float acc = sb[0];
            #pragma unroll 8
            for (int d = 0; d < NN; d++) acc += g_out[t * NN + d] * sw[d];
            out[score_off + t] = acc;
        }
    }
}

// ---------------- launch ----------------
extern "C" void kernel_launch(void* const* d_in, const int* in_sizes, int n_in,
                              void* d_out, int out_size) {
    const float* x   = (const float*)d_in[0];
    const float* ipw = (const float*)d_in[1];
    const float* ipb = (const float*)d_in[2];
    const float* ns  = (const float*)d_in[3];
    const float* ev  = (const float*)d_in[4];
    const float* rw  = (const float*)d_in[5];
    const float* rb  = (const float*)d_in[6];
    const float* sw  = (const float*)d_in[7];
    const float* sb  = (const float*)d_in[8];
    float* out = (float*)d_out;

    k_fused1<<<NN + 1 + 144, 256>>>(ev, ns, x, ipw);
    k_final <<<BB, 1024>>>(ipb);
    k_heads <<<289, 256>>>(rw, rb, sw, sb, out, out_size - BB);
}